// round 8
// baseline (speedup 1.0000x reference)
#include <cuda_runtime.h>
#include <math.h>

#define BETA 0.1f

// One block = one output tile = one pure contiguous 16 KB store stream.
// Block 2i   -> places[i]   (no log/max needed, just the raw outer product)
// Block 2i+1 -> sampled[i]  (Gumbel-argmax mask, *100 folded into h)
// 128 threads per block; 8 float4 store iterations each.
__global__ __launch_bounds__(128, 16)
void spatial_sampler_kernel(const float* __restrict__ x_cat,
                            const float* __restrict__ noise,
                            float* __restrict__ out,
                            long long half_elems)
{
    __shared__ float sh[128];   // [0:64) h (pre-scaled for sampled), [64:128) v
    __shared__ float wmax[4];

    const int bid  = blockIdx.x;
    const int bp   = bid >> 1;          // tile id 0..8191
    const bool samp = (bid & 1);
    const int tid  = threadIdx.x;

    const long long base = (long long)bp * 128;
    const float xv = x_cat[base + tid];

    if (!samp) {
        sh[tid] = xv;
    } else {
        const float lp = logf(xv) + BETA * noise[base + tid];
        float m = lp;
        #pragma unroll
        for (int off = 16; off > 0; off >>= 1)
            m = fmaxf(m, __shfl_xor_sync(0xffffffffu, m, off));
        if ((tid & 31) == 0) wmax[tid >> 5] = m;
        __syncthreads();
        const float rowmax = (tid < 64) ? fmaxf(wmax[0], wmax[1])
                                        : fmaxf(wmax[2], wmax[3]);
        float s = (lp == rowmax) ? xv : 0.f;
        sh[tid] = (tid < 64) ? s * 100.0f : s;   // fold *100 into h half
    }
    __syncthreads();

    // --- pure contiguous 16 KB store burst for this block ---
    float4* dst = reinterpret_cast<float4*>(
        out + (samp ? half_elems : 0) + (long long)bp * 4096);
    const float4* v4 = reinterpret_cast<const float4*>(&sh[64]);

    #pragma unroll
    for (int it = 0; it < 8; ++it) {
        const int i  = tid + it * 128;   // float4 index 0..1023
        const int j  = i >> 4;           // row 0..63
        const int c4 = i & 15;           // float4 col 0..15

        const float hj = sh[j];
        float4 vv = v4[c4];
        float4 o;
        o.x = hj * vv.x; o.y = hj * vv.y; o.z = hj * vv.z; o.w = hj * vv.w;
        dst[i] = o;
    }
}

extern "C" void kernel_launch(void* const* d_in, const int* in_sizes, int n_in,
                              void* d_out, int out_size)
{
    const float* x_cat = (const float*)d_in[0];
    const float* noise = (const float*)d_in[1];
    float* out = (float*)d_out;

    const long long half = (long long)out_size / 2;
    const int tiles = in_sizes[0] / 128;   // 8192

    spatial_sampler_kernel<<<tiles * 2, 128>>>(x_cat, noise, out, half);
}

// round 9
// speedup vs baseline: 1.0211x; 1.0211x over previous
#include <cuda_runtime.h>
#include <math.h>

#define BETA 0.1f

// Best structure (R5: de-interleaved half-block per output tensor) with
// 256-bit stores (sm_10x STG.E.256): each thread stores 32 contiguous bytes,
// a warp emits 1024 contiguous bytes per iteration.
__global__ __launch_bounds__(256, 8)
void spatial_sampler_kernel(const float* __restrict__ x_cat,
                            const float* __restrict__ noise,
                            float* __restrict__ out,
                            long long half_elems)
{
    __shared__ float sx[128];   // [0:64) h row, [64:128) v row
    __shared__ float ss[128];   // masked rows (h part pre-scaled by 100)
    __shared__ float wmax[4];

    const int bp  = blockIdx.x;
    const int tid = threadIdx.x;

    const float* xrow = x_cat + (long long)bp * 128;
    const float* nrow = noise + (long long)bp * 128;

    // --- load + log_pdf + per-row max (each 64-wide row = 2 warps) ---
    float lp = -INFINITY;
    float xv = 0.f;
    if (tid < 128) {
        xv = xrow[tid];
        lp = logf(xv) + BETA * nrow[tid];
        sx[tid] = xv;
    }
    float m = lp;
    #pragma unroll
    for (int off = 16; off > 0; off >>= 1)
        m = fmaxf(m, __shfl_xor_sync(0xffffffffu, m, off));
    if (tid < 128 && (tid & 31) == 0)
        wmax[tid >> 5] = m;
    __syncthreads();

    if (tid < 128) {
        float rowmax = (tid < 64) ? fmaxf(wmax[0], wmax[1])
                                  : fmaxf(wmax[2], wmax[3]);
        float s = (lp == rowmax) ? xv : 0.f;
        ss[tid] = (tid < 64) ? s * 100.0f : s;   // fold *100 into h half
    }
    __syncthreads();

    // --- de-interleaved 256-bit stores: half-block per output tensor ---
    const int  half_tid = tid & 127;          // 0..127 within half-block
    const bool is_samp  = (tid >= 128);

    const float* hsrc = is_samp ? ss : sx;
    const float4* v4  = reinterpret_cast<const float4*>(is_samp ? &ss[64] : &sx[64]);
    float* dst = out + (is_samp ? half_elems : 0) + (long long)bp * 4096;

    #pragma unroll
    for (int it = 0; it < 4; ++it) {
        const int i  = half_tid + it * 128;   // v8 index 0..511
        const int j  = i >> 3;                // row 0..63
        const int c8 = i & 7;                 // 8-float column group 0..7

        const float hj = hsrc[j];
        float4 va = v4[c8 * 2];
        float4 vb = v4[c8 * 2 + 1];
        float o0 = hj * va.x, o1 = hj * va.y, o2 = hj * va.z, o3 = hj * va.w;
        float o4 = hj * vb.x, o5 = hj * vb.y, o6 = hj * vb.z, o7 = hj * vb.w;

        asm volatile(
            "st.global.v8.f32 [%0], {%1,%2,%3,%4,%5,%6,%7,%8};"
            :: "l"(dst + (long long)i * 8),
               "f"(o0), "f"(o1), "f"(o2), "f"(o3),
               "f"(o4), "f"(o5), "f"(o6), "f"(o7)
            : "memory");
    }
}

extern "C" void kernel_launch(void* const* d_in, const int* in_sizes, int n_in,
                              void* d_out, int out_size)
{
    const float* x_cat = (const float*)d_in[0];
    const float* noise = (const float*)d_in[1];
    float* out = (float*)d_out;

    const long long half = (long long)out_size / 2;
    const int tiles = in_sizes[0] / 128;   // 8192 (b,p) tiles

    spatial_sampler_kernel<<<tiles, 256>>>(x_cat, noise, out, half);
}